// round 6
// baseline (speedup 1.0000x reference)
#include <cuda_runtime.h>
#include <cuda_fp16.h>
#include <cstdint>

#define NN 64
#define HH 512
#define TB 128

#define PIT1 136   // pitch (halves) for K=64 hi|lo tiles (X/A3, W13 chunks)
#define PIT2 264   // pitch (halves) for K=128 hi|lo tiles (A2, W2 chunk)

// shared memory byte offsets
#define OFF_XN    0          // 128 floats
#define OFF_EPI   512        // 512 * float4 = 8192
#define OFF_X     8704       // 128*136*2 = 34816  (X hi|lo; later A3)
#define OFF_W13A  43520      // W1/W3 chunk buf A
#define OFF_W13B  78336      // W1/W3 chunk buf B
#define OFF_W2    113152     // 64*264*2 = 33792 (W2 chunk; later reduce buf)
#define OFF_A2    146944     // 128*264*2 = 67584
#define SMEM_BYTES 214528

// -------- device scratch: pre-split fp16 weights + packed epilogue --------
__device__ __half W1s_g[64 * 4 * 128 * 128];   // [n][hc][row][64hi|64lo]
__device__ __half W2s_g[64 * 4 * 64 * 256];    // [n][kc][m][128hi|128lo]
__device__ __half W3s_g[64 * 4 * 128 * 128];   // [n][hc][row][64hi|64lo]
__device__ float4 EPI_g[64 * 512];             // (w3col, b3, w4, 0)

// ---------------------------------------------------------------- helpers
__device__ __forceinline__ uint32_t smem_u32(const void* p) {
    uint32_t a;
    asm("{ .reg .u64 t; cvta.to.shared.u64 t, %1; cvt.u32.u64 %0, t; }"
        : "=r"(a) : "l"(p));
    return a;
}
__device__ __forceinline__ void cpa16(uint32_t s, const void* g) {
    asm volatile("cp.async.cg.shared.global [%0], [%1], 16;" :: "r"(s), "l"(g));
}
#define CP_COMMIT() asm volatile("cp.async.commit_group;" ::: "memory")
#define CP_WAIT(N)  asm volatile("cp.async.wait_group %0;" :: "n"(N) : "memory")

__device__ __forceinline__ void mma16816(float c[4],
                                         uint32_t a0, uint32_t a1, uint32_t a2, uint32_t a3,
                                         uint32_t b0, uint32_t b1) {
    asm volatile(
        "mma.sync.aligned.m16n8k16.row.col.f32.f16.f16.f32 "
        "{%0,%1,%2,%3}, {%4,%5,%6,%7}, {%8,%9}, {%0,%1,%2,%3};\n"
        : "+f"(c[0]), "+f"(c[1]), "+f"(c[2]), "+f"(c[3])
        : "r"(a0), "r"(a1), "r"(a2), "r"(a3), "r"(b0), "r"(b1));
}
__device__ __forceinline__ void split_store2(__half* hiP, __half* loP, float a, float b) {
    __half ha = __float2half_rn(a), hb = __float2half_rn(b);
    __half la = __float2half_rn(a - __half2float(ha));
    __half lb = __float2half_rn(b - __half2float(hb));
    *(__half2*)hiP = __halves2half2(ha, hb);
    *(__half2*)loP = __halves2half2(la, lb);
}
__device__ __forceinline__ void split_store4(__half* hiP, __half* loP, float4 v) {
    split_store2(hiP,     loP,     v.x, v.y);
    split_store2(hiP + 2, loP + 2, v.z, v.w);
}

// K=64 hi|lo GEMM, 3 compensation passes. Warp: C[32b x 64n].
// Row mapping: acc[mt][j][0..1] -> row bq*32+mt*16+g ; [2..3] -> +8
__device__ __forceinline__ void gemm64(const __half* At, const __half* Wt,
                                       int bq, int hh, int g, int tg,
                                       float acc[2][8][4]) {
    const int pa[3] = {0, 64, 0};
    const int pb[3] = {0, 0, 64};
    #pragma unroll
    for (int p = 0; p < 3; ++p) {
        #pragma unroll
        for (int ks = 0; ks < 4; ++ks) {
            const int kA = pa[p] + ks * 16 + tg * 2;
            const int kB = pb[p] + ks * 16 + tg * 2;
            uint32_t a[2][4];
            #pragma unroll
            for (int mt = 0; mt < 2; ++mt) {
                const __half* base = At + (bq * 32 + mt * 16 + g) * PIT1 + kA;
                a[mt][0] = *(const uint32_t*)(base);
                a[mt][1] = *(const uint32_t*)(base + 8 * PIT1);
                a[mt][2] = *(const uint32_t*)(base + 8);
                a[mt][3] = *(const uint32_t*)(base + 8 * PIT1 + 8);
            }
            #pragma unroll
            for (int j = 0; j < 8; ++j) {
                const __half* bb = Wt + (hh * 64 + j * 8 + g) * PIT1 + kB;
                uint32_t b0 = *(const uint32_t*)(bb);
                uint32_t b1 = *(const uint32_t*)(bb + 8);
                mma16816(acc[0][j], a[0][0], a[0][1], a[0][2], a[0][3], b0, b1);
                mma16816(acc[1][j], a[1][0], a[1][1], a[1][2], a[1][3], b0, b1);
            }
        }
    }
}

// smem tile fills via cp.async
__device__ __forceinline__ void copy_w13(uint32_t dst, const __half* src, int tid) {
    #pragma unroll 2
    for (int i = tid; i < 2048; i += 256) {
        const int row = i >> 4, gr = i & 15;
        cpa16(dst + row * 272 + gr * 16, src + row * 128 + gr * 8);
    }
}
__device__ __forceinline__ void copy_w2(uint32_t dst, const __half* src, int tid) {
    #pragma unroll 2
    for (int i = tid; i < 2048; i += 256) {
        const int row = i >> 5, gr = i & 31;
        cpa16(dst + row * 528 + gr * 16, src + row * 256 + gr * 8);
    }
}

// ---------------------------------------------------------------- prep kernel
__global__ __launch_bounds__(256)
void prep_kernel(const float* __restrict__ W1, const float* __restrict__ W2,
                 const float* __restrict__ W3, const float* __restrict__ b3,
                 const float* __restrict__ W4)
{
    const int t = blockIdx.x * 256 + threadIdx.x;   // 0 .. 524287
    // ---- W1 -> W1s_g ----
    {
        const int n = t >> 13, r = (t >> 4) & 511, k4 = (t & 15) * 4;
        float4 v = *(const float4*)(W1 + ((n << 9) + r) * 64 + k4);
        __half* dst = W1s_g + ((((n * 4 + (r >> 7)) * 128) + (r & 127)) << 7);
        split_store4(dst + k4, dst + 64 + k4, v);
    }
    // ---- W2 -> W2s_g ----
    {
        const int n = t >> 13, m = (t >> 7) & 63, k4 = (t & 127) * 4;
        float4 v = *(const float4*)(W2 + ((n << 6) + m) * 512 + k4);
        __half* dst = W2s_g + (((n * 4 + (k4 >> 7)) * 64 + m) << 8);
        const int kk = k4 & 127;
        split_store4(dst + kk, dst + 128 + kk, v);
    }
    // ---- W3 first 64 cols -> W3s_g ----
    {
        const int n = t >> 13, r = (t >> 4) & 511, k4 = (t & 15) * 4;
        float4 v = *(const float4*)(W3 + (((n << 9) + r) << 7) + k4);
        __half* dst = W3s_g + ((((n * 4 + (r >> 7)) * 128) + (r & 127)) << 7);
        split_store4(dst + k4, dst + 64 + k4, v);
    }
    // ---- epilogue pack ----
    if (t < 32768) {
        const int n = t >> 9, h = t & 511;
        EPI_g[t] = make_float4(W3[(((n << 9) + h) << 7) + 64 + n],
                               b3[(n << 9) + h],
                               W4[(n << 9) + h], 0.0f);
    }
}

// ---------------------------------------------------------------- main kernel
__global__ __launch_bounds__(256, 1)
void ctp_hmma_kernel(const float* __restrict__ x,
                     const float* __restrict__ b4,
                     float* __restrict__ out)
{
    extern __shared__ char sm[];
    const uint32_t sb = smem_u32(sm);
    float*  sXn  = (float*)(sm + OFF_XN);
    float4* sEpi = (float4*)(sm + OFF_EPI);
    __half* Xt   = (__half*)(sm + OFF_X);
    __half* W2t  = (__half*)(sm + OFF_W2);
    __half* A2t  = (__half*)(sm + OFF_A2);
    __half* w13p[2] = {(__half*)(sm + OFF_W13A), (__half*)(sm + OFF_W13B)};
    const uint32_t w13s[2] = {sb + OFF_W13A, sb + OFF_W13B};

    const int tid  = threadIdx.x;
    const int wid  = tid >> 5;
    const int lane = tid & 31;
    const int g    = lane >> 2;
    const int tg   = lane & 3;
    const int bq   = wid & 3;
    const int hh   = wid >> 2;
    const int n    = blockIdx.x;
    const int r0   = blockIdx.y * TB;

    const __half* W1n = W1s_g + n * (4 * 128 * 128);
    const __half* W2n = W2s_g + n * (4 * 64 * 256);
    const __half* W3n = W3s_g + n * (4 * 128 * 128);

    // prefetch W1 chunk 0
    copy_w13(w13s[0], W1n, tid);
    CP_COMMIT();

    // ---- prologue: X tile (col n zeroed, xn captured) + epilogue table ----
    {
        const int row = tid >> 1, hf = tid & 1;
        const float* xr = x + (r0 + row) * NN + hf * 32;
        #pragma unroll
        for (int i = 0; i < 8; ++i) {
            const int c = hf * 32 + i * 4;
            float4 v = *(const float4*)(xr + i * 4);
            if (n >= c && n < c + 4) {
                float vv[4] = {v.x, v.y, v.z, v.w};
                sXn[row] = vv[n - c];
                vv[n - c] = 0.0f;
                v = make_float4(vv[0], vv[1], vv[2], vv[3]);
            }
            split_store4(Xt + row * PIT1 + c, Xt + row * PIT1 + 64 + c, v);
        }
    }
    for (int idx = tid; idx < HH; idx += 256)
        sEpi[idx] = EPI_g[n * 512 + idx];
    const float b4n = b4[n];

    float acc2[2][4][4] = {};   // D2 [128b x 64m] warp slice, persistent

    // =================== Stages 1+2 over 4 H-chunks of 128 ===================
    for (int hc = 0; hc < 4; ++hc) {
        CP_WAIT(0);
        __syncthreads();   // W13[cur] arrived everywhere; W2/A2 free

        copy_w2(sb + OFF_W2, W2n + hc * (64 * 256), tid);
        CP_COMMIT();                       // group: W2[hc]
        if (hc < 3) copy_w13(w13s[(hc + 1) & 1], W1n + (hc + 1) * (128 * 128), tid);
        CP_COMMIT();                       // group: W13[hc+1] (possibly empty)

        // stage 1: D1 chunk [128b x 128h] = X @ W1c^T  (overlaps the cp.asyncs)
        float acc1[2][8][4] = {};
        gemm64(Xt, w13p[hc & 1], bq, hh, g, tg, acc1);

        // relu + split-store into A2
        #pragma unroll
        for (int mt = 0; mt < 2; ++mt) {
            const int r = bq * 32 + mt * 16 + g;
            #pragma unroll
            for (int j = 0; j < 8; ++j) {
                const int c = hh * 64 + j * 8 + tg * 2;
                split_store2(A2t + r * PIT2 + c,       A2t + r * PIT2 + 128 + c,
                             fmaxf(acc1[mt][j][0], 0.f), fmaxf(acc1[mt][j][1], 0.f));
                split_store2(A2t + (r + 8) * PIT2 + c, A2t + (r + 8) * PIT2 + 128 + c,
                             fmaxf(acc1[mt][j][2], 0.f), fmaxf(acc1[mt][j][3], 0.f));
            }
        }
        CP_WAIT(1);        // W2[hc] complete (FIFO; W13 prefetch may still fly)
        __syncthreads();   // A2 + W2 visible to all

        // stage 2 partial: D2 += A2chunk @ W2chunk^T (K=128, 3 passes)
        {
            const int pa[3] = {0, 128, 0};
            const int pb[3] = {0, 0, 128};
            #pragma unroll
            for (int p = 0; p < 3; ++p) {
                #pragma unroll
                for (int ks = 0; ks < 8; ++ks) {
                    const int kA = pa[p] + ks * 16 + tg * 2;
                    const int kB = pb[p] + ks * 16 + tg * 2;
                    uint32_t a[2][4];
                    #pragma unroll
                    for (int mt = 0; mt < 2; ++mt) {
                        const __half* base = A2t + (bq * 32 + mt * 16 + g) * PIT2 + kA;
                        a[mt][0] = *(const uint32_t*)(base);
                        a[mt][1] = *(const uint32_t*)(base + 8 * PIT2);
                        a[mt][2] = *(const uint32_t*)(base + 8);
                        a[mt][3] = *(const uint32_t*)(base + 8 * PIT2 + 8);
                    }
                    #pragma unroll
                    for (int j = 0; j < 4; ++j) {
                        const __half* bb = W2t + (hh * 32 + j * 8 + g) * PIT2 + kB;
                        uint32_t b0 = *(const uint32_t*)(bb);
                        uint32_t b1 = *(const uint32_t*)(bb + 8);
                        mma16816(acc2[0][j], a[0][0], a[0][1], a[0][2], a[0][3], b0, b1);
                        mma16816(acc2[1][j], a[1][0], a[1][1], a[1][2], a[1][3], b0, b1);
                    }
                }
            }
        }
    }

    // ---- A3 = relu(D2) -> hi/lo into X buffer ----
    #pragma unroll
    for (int mt = 0; mt < 2; ++mt) {
        const int r = bq * 32 + mt * 16 + g;
        #pragma unroll
        for (int j = 0; j < 4; ++j) {
            const int c = hh * 32 + j * 8 + tg * 2;
            split_store2(Xt + r * PIT1 + c,       Xt + r * PIT1 + 64 + c,
                         fmaxf(acc2[mt][j][0], 0.f), fmaxf(acc2[mt][j][1], 0.f));
            split_store2(Xt + (r + 8) * PIT1 + c, Xt + (r + 8) * PIT1 + 64 + c,
                         fmaxf(acc2[mt][j][2], 0.f), fmaxf(acc2[mt][j][3], 0.f));
        }
    }
    // prefetch W3 chunk 0 (reuses W13 buf 0; all stage-1 readers long done)
    copy_w13(w13s[0], W3n, tid);
    CP_COMMIT();

    // xn per accumulator slot: rows {g, 8+g, 16+g, 24+g}  (FIX: R5 had 1<->2 swapped)
    float xnv[4];
    #pragma unroll
    for (int i = 0; i < 4; ++i) xnv[i] = sXn[bq * 32 + i * 8 + g];

    // =================== Stage 3 over 4 H-chunks, fused epilogue ===================
    // rowSum slot -> row: [0]=g, [1]=8+g (mt=0 halves), [2]=16+g, [3]=24+g (mt=1)
    float rowSum[4] = {};
    for (int hc = 0; hc < 4; ++hc) {
        CP_WAIT(0);
        __syncthreads();   // W3[cur] arrived; A3 visible (first iter)
        if (hc < 3) copy_w13(w13s[(hc + 1) & 1], W3n + (hc + 1) * (128 * 128), tid);
        CP_COMMIT();

        float acc3[2][8][4] = {};
        gemm64(Xt, w13p[hc & 1], bq, hh, g, tg, acc3);

        #pragma unroll
        for (int j = 0; j < 8; ++j) {
            const int colb = hc * 128 + hh * 64 + j * 8 + tg * 2;
            const float4 e0 = sEpi[colb];
            const float4 e1 = sEpi[colb + 1];
            #pragma unroll
            for (int mt = 0; mt < 2; ++mt) {
                float z;
                z = acc3[mt][j][0] + xnv[mt * 2]     * e0.x + e0.y;   // row mt*16+g
                rowSum[mt * 2]     += fmaxf(z, 0.f) * e0.z;
                z = acc3[mt][j][1] + xnv[mt * 2]     * e1.x + e1.y;
                rowSum[mt * 2]     += fmaxf(z, 0.f) * e1.z;
                z = acc3[mt][j][2] + xnv[mt * 2 + 1] * e0.x + e0.y;   // row mt*16+8+g
                rowSum[mt * 2 + 1] += fmaxf(z, 0.f) * e0.z;
                z = acc3[mt][j][3] + xnv[mt * 2 + 1] * e1.x + e1.y;
                rowSum[mt * 2 + 1] += fmaxf(z, 0.f) * e1.z;
            }
        }
    }
    __syncthreads();   // all W13/A2/W2 consumers done; W2 region free for reduce

    // reduce over the 4 k-threads of each group, then over the two column halves
    float* Pred = (float*)(sm + OFF_W2);   // [2][128]
    #pragma unroll
    for (int i = 0; i < 4; ++i) {
        float v = rowSum[i];
        v += __shfl_xor_sync(0xffffffffu, v, 1);
        v += __shfl_xor_sync(0xffffffffu, v, 2);
        // rowSum[i] corresponds to row bq*32 + i*8 + g (i in {0,1}=mt0, {2,3}=mt1)
        const int rr = bq * 32 + ((i & 1) ? 8 : 0) + ((i >> 1) ? 16 : 0) + g;
        if (tg == 0) Pred[hh * 128 + rr] = v;
    }
    __syncthreads();
    if (tid < 128) {
        const float tot = Pred[tid] + Pred[128 + tid];
        out[(r0 + tid) * NN + n] = fmaxf(tot + b4n, 0.0f);
    }
}

extern "C" void kernel_launch(void* const* d_in, const int* in_sizes, int n_in,
                              void* d_out, int out_size)
{
    const float* x  = (const float*)d_in[0];
    const float* W1 = (const float*)d_in[1];
    const float* W2 = (const float*)d_in[2];
    const float* W3 = (const float*)d_in[3];
    const float* b3 = (const float*)d_in[4];
    const float* W4 = (const float*)d_in[5];
    const float* b4 = (const float*)d_in[6];
    float* out = (float*)d_out;

    prep_kernel<<<2048, 256>>>(W1, W2, W3, b3, W4);

    cudaFuncSetAttribute(ctp_hmma_kernel,
                         cudaFuncAttributeMaxDynamicSharedMemorySize, SMEM_BYTES);
    dim3 grid(NN, 1024 / TB);   // (64 nodes, 8 batch tiles of 128)
    ctp_hmma_kernel<<<grid, 256, SMEM_BYTES>>>(x, b4, out);
}

// round 7
// speedup vs baseline: 2.1787x; 2.1787x over previous
#include <cuda_runtime.h>
#include <cuda_fp16.h>
#include <cstdint>

#define NN 64
#define HH 512
#define TB 128

#define PIT1  136  // X/A3 tiles: 64 hi | 64 lo | 8 pad   (halves)
#define PITW  72   // W1/W3 chunk: 64 hi | 8 pad
#define PIT2  264  // A2 tile: 128 hi | 128 lo | 8 pad
#define PITW2 136  // W2 chunk: 128 hi | 8 pad

// shared memory byte offsets
#define OFF_XN    0          // 128 floats
#define OFF_EPI   512        // 512 * float4 = 8192
#define OFF_X     8704       // 128*136*2 = 34816  (X hi|lo; later A3)
#define OFF_W13   43520      // 128*72*2  = 18432  (W1 / W3 chunk, hi only)
#define OFF_W2    61952      // 64*136*2  = 17408  (W2 chunk, hi only; later reduce buf)
#define OFF_A2    79360      // 128*264*2 = 67584  (relu(H1) chunk, hi|lo)
#define SMEM_BYTES 146944

// ---------------------------------------------------------------- helpers
__device__ __forceinline__ void mma16816(float c[4],
                                         uint32_t a0, uint32_t a1, uint32_t a2, uint32_t a3,
                                         uint32_t b0, uint32_t b1) {
    asm volatile(
        "mma.sync.aligned.m16n8k16.row.col.f32.f16.f16.f32 "
        "{%0,%1,%2,%3}, {%4,%5,%6,%7}, {%8,%9}, {%0,%1,%2,%3};\n"
        : "+f"(c[0]), "+f"(c[1]), "+f"(c[2]), "+f"(c[3])
        : "r"(a0), "r"(a1), "r"(a2), "r"(a3), "r"(b0), "r"(b1));
}

// activations: split into fp16 hi/lo
__device__ __forceinline__ void split_store2(__half* hiP, __half* loP, float a, float b) {
    __half ha = __float2half_rn(a), hb = __float2half_rn(b);
    __half la = __float2half_rn(a - __half2float(ha));
    __half lb = __float2half_rn(b - __half2float(hb));
    *(__half2*)hiP = __halves2half2(ha, hb);
    *(__half2*)loP = __halves2half2(la, lb);
}
__device__ __forceinline__ void split_store4(__half* hiP, __half* loP, float4 v) {
    split_store2(hiP,     loP,     v.x, v.y);
    split_store2(hiP + 2, loP + 2, v.z, v.w);
}
// weights: fp16 hi only, 4 consecutive values as one 8B store
__device__ __forceinline__ void hstore4(__half* p, float4 v) {
    __half2 h01 = __floats2half2_rn(v.x, v.y);
    __half2 h23 = __floats2half2_rn(v.z, v.w);
    *(uint2*)p = make_uint2(*(uint32_t*)&h01, *(uint32_t*)&h23);
}

// K=64 2-pass GEMM: C[32b x 64n] += (A_hi + A_lo) @ W_hi^T
// A tile pitch PIT1 (hi at 0, lo at +64); W tile pitch PITW (hi only).
// Row mapping: acc[mt][j][0..1] -> row bq*32+mt*16+g ; [2..3] -> +8
__device__ __forceinline__ void gemm64_2p(const __half* At, const __half* Wt,
                                          int bq, int hh, int g, int tg,
                                          float acc[2][8][4]) {
    #pragma unroll
    for (int ks = 0; ks < 4; ++ks) {
        const int k = ks * 16 + tg * 2;
        uint32_t ah[2][4], al[2][4];
        #pragma unroll
        for (int mt = 0; mt < 2; ++mt) {
            const __half* base = At + (bq * 32 + mt * 16 + g) * PIT1 + k;
            ah[mt][0] = *(const uint32_t*)(base);
            ah[mt][1] = *(const uint32_t*)(base + 8 * PIT1);
            ah[mt][2] = *(const uint32_t*)(base + 8);
            ah[mt][3] = *(const uint32_t*)(base + 8 * PIT1 + 8);
            al[mt][0] = *(const uint32_t*)(base + 64);
            al[mt][1] = *(const uint32_t*)(base + 8 * PIT1 + 64);
            al[mt][2] = *(const uint32_t*)(base + 72);
            al[mt][3] = *(const uint32_t*)(base + 8 * PIT1 + 72);
        }
        #pragma unroll
        for (int j = 0; j < 8; ++j) {
            const __half* bb = Wt + (hh * 64 + j * 8 + g) * PITW + k;
            uint32_t b0 = *(const uint32_t*)(bb);
            uint32_t b1 = *(const uint32_t*)(bb + 8);
            mma16816(acc[0][j], ah[0][0], ah[0][1], ah[0][2], ah[0][3], b0, b1);
            mma16816(acc[0][j], al[0][0], al[0][1], al[0][2], al[0][3], b0, b1);
            mma16816(acc[1][j], ah[1][0], ah[1][1], ah[1][2], ah[1][3], b0, b1);
            mma16816(acc[1][j], al[1][0], al[1][1], al[1][2], al[1][3], b0, b1);
        }
    }
}

// ---------------------------------------------------------------- kernel
__global__ __launch_bounds__(256, 1)
void ctp_hmma_kernel(const float* __restrict__ x,
                     const float* __restrict__ W1,
                     const float* __restrict__ W2,
                     const float* __restrict__ W3,
                     const float* __restrict__ b3,
                     const float* __restrict__ W4,
                     const float* __restrict__ b4,
                     float* __restrict__ out)
{
    extern __shared__ char sm[];
    float*  sXn  = (float*)(sm + OFF_XN);
    float4* sEpi = (float4*)(sm + OFF_EPI);
    __half* Xt   = (__half*)(sm + OFF_X);
    __half* W13t = (__half*)(sm + OFF_W13);
    __half* W2t  = (__half*)(sm + OFF_W2);
    __half* A2t  = (__half*)(sm + OFF_A2);

    const int tid  = threadIdx.x;
    const int lane = tid & 31;
    const int wid  = tid >> 5;
    const int g    = lane >> 2;
    const int tg   = lane & 3;
    const int bq   = wid & 3;
    const int hh   = wid >> 2;
    const int n    = blockIdx.x;
    const int r0   = blockIdx.y * TB;

    // ---- prologue: X tile (col n zeroed, xn captured) + epilogue vectors ----
    {
        const int row = tid >> 1, hf = tid & 1;
        const float* xr = x + (r0 + row) * NN + hf * 32;
        #pragma unroll
        for (int i = 0; i < 8; ++i) {
            const int c = hf * 32 + i * 4;
            float4 v = *(const float4*)(xr + i * 4);
            if (n >= c && n < c + 4) {
                float vv[4] = {v.x, v.y, v.z, v.w};
                sXn[row] = vv[n - c];
                vv[n - c] = 0.0f;
                v = make_float4(vv[0], vv[1], vv[2], vv[3]);
            }
            split_store4(Xt + row * PIT1 + c, Xt + row * PIT1 + 64 + c, v);
        }
    }
    for (int idx = tid; idx < HH; idx += 256)
        sEpi[idx] = make_float4(W3[(n * HH + idx) * 128 + 64 + n],
                                b3[n * HH + idx],
                                W4[n * HH + idx], 0.0f);
    const float b4n = b4[n];

    float acc2[2][4][4] = {};   // D2 [128b x 64m] warp slice, persistent

    // =================== Stages 1+2 over 4 H-chunks of 128 ===================
    for (int hc = 0; hc < 4; ++hc) {
        __syncthreads();   // previous chunk's consumers done before overwriting
        // W1 chunk [128h x 64k] -> hi only
        for (int idx = tid; idx < 2048; idx += 256) {
            const int row = idx >> 4, q = (idx & 15) * 4;
            float4 v = *(const float4*)(W1 + n * (HH * NN) + (hc * 128 + row) * NN + q);
            hstore4(W13t + row * PITW + q, v);
        }
        // W2 chunk [64m x 128k] -> hi only
        for (int idx = tid; idx < 2048; idx += 256) {
            const int m = idx >> 5, q = (idx & 31) * 4;
            float4 v = *(const float4*)(W2 + n * (NN * HH) + m * HH + hc * 128 + q);
            hstore4(W2t + m * PITW2 + q, v);
        }
        __syncthreads();

        // ---- stage 1: D1 chunk [128b x 128h] = X @ W1c^T ----
        float acc1[2][8][4] = {};
        gemm64_2p(Xt, W13t, bq, hh, g, tg, acc1);

        // relu + split-store into A2 (hi at c, lo at 128+c)
        #pragma unroll
        for (int mt = 0; mt < 2; ++mt) {
            const int r = bq * 32 + mt * 16 + g;
            #pragma unroll
            for (int j = 0; j < 8; ++j) {
                const int c = hh * 64 + j * 8 + tg * 2;
                split_store2(A2t + r * PIT2 + c,       A2t + r * PIT2 + 128 + c,
                             fmaxf(acc1[mt][j][0], 0.f), fmaxf(acc1[mt][j][1], 0.f));
                split_store2(A2t + (r + 8) * PIT2 + c, A2t + (r + 8) * PIT2 + 128 + c,
                             fmaxf(acc1[mt][j][2], 0.f), fmaxf(acc1[mt][j][3], 0.f));
            }
        }
        __syncthreads();

        // ---- stage 2 partial: D2 += A2chunk @ W2chunk^T (K=128, 2 passes) ----
        #pragma unroll
        for (int ks = 0; ks < 8; ++ks) {
            const int k = ks * 16 + tg * 2;
            uint32_t ah[2][4], al[2][4];
            #pragma unroll
            for (int mt = 0; mt < 2; ++mt) {
                const __half* base = A2t + (bq * 32 + mt * 16 + g) * PIT2 + k;
                ah[mt][0] = *(const uint32_t*)(base);
                ah[mt][1] = *(const uint32_t*)(base + 8 * PIT2);
                ah[mt][2] = *(const uint32_t*)(base + 8);
                ah[mt][3] = *(const uint32_t*)(base + 8 * PIT2 + 8);
                al[mt][0] = *(const uint32_t*)(base + 128);
                al[mt][1] = *(const uint32_t*)(base + 8 * PIT2 + 128);
                al[mt][2] = *(const uint32_t*)(base + 136);
                al[mt][3] = *(const uint32_t*)(base + 8 * PIT2 + 136);
            }
            #pragma unroll
            for (int j = 0; j < 4; ++j) {
                const __half* bb = W2t + (hh * 32 + j * 8 + g) * PITW2 + k;
                uint32_t b0 = *(const uint32_t*)(bb);
                uint32_t b1 = *(const uint32_t*)(bb + 8);
                mma16816(acc2[0][j], ah[0][0], ah[0][1], ah[0][2], ah[0][3], b0, b1);
                mma16816(acc2[0][j], al[0][0], al[0][1], al[0][2], al[0][3], b0, b1);
                mma16816(acc2[1][j], ah[1][0], ah[1][1], ah[1][2], ah[1][3], b0, b1);
                mma16816(acc2[1][j], al[1][0], al[1][1], al[1][2], al[1][3], b0, b1);
            }
        }
    }

    // ---- A3 = relu(D2) -> hi/lo into X buffer (X dead after stage 1) ----
    __syncthreads();
    #pragma unroll
    for (int mt = 0; mt < 2; ++mt) {
        const int r = bq * 32 + mt * 16 + g;
        #pragma unroll
        for (int j = 0; j < 4; ++j) {
            const int c = hh * 32 + j * 8 + tg * 2;
            split_store2(Xt + r * PIT1 + c,       Xt + r * PIT1 + 64 + c,
                         fmaxf(acc2[mt][j][0], 0.f), fmaxf(acc2[mt][j][1], 0.f));
            split_store2(Xt + (r + 8) * PIT1 + c, Xt + (r + 8) * PIT1 + 64 + c,
                         fmaxf(acc2[mt][j][2], 0.f), fmaxf(acc2[mt][j][3], 0.f));
        }
    }

    // xn per accumulator row group: rows {g, 8+g, 16+g, 24+g}
    float xnv[4];
    #pragma unroll
    for (int i = 0; i < 4; ++i) xnv[i] = sXn[bq * 32 + i * 8 + g];

    // =================== Stage 3 over 4 H-chunks, fused epilogue ===================
    float rowSum[4] = {};
    for (int hc = 0; hc < 4; ++hc) {
        __syncthreads();   // prior W13 readers done; (first iter: A3 stores ordered)
        for (int idx = tid; idx < 2048; idx += 256) {
            const int row = idx >> 4, q = (idx & 15) * 4;
            float4 v = *(const float4*)(W3 + n * (HH * 128) + (hc * 128 + row) * 128 + q);
            hstore4(W13t + row * PITW + q, v);
        }
        __syncthreads();

        float acc3[2][8][4] = {};
        gemm64_2p(Xt, W13t, bq, hh, g, tg, acc3);

        // z = d3 + xn*w3col + b3 ; rowSum += relu(z)*w4
        #pragma unroll
        for (int j = 0; j < 8; ++j) {
            const int colb = hc * 128 + hh * 64 + j * 8 + tg * 2;
            const float4 e0 = sEpi[colb];
            const float4 e1 = sEpi[colb + 1];
            #pragma unroll
            for (int mt = 0; mt < 2; ++mt) {
                float z;
                z = acc3[mt][j][0] + xnv[mt * 2]     * e0.x + e0.y;   // row mt*16+g
                rowSum[mt * 2]     += fmaxf(z, 0.f) * e0.z;
                z = acc3[mt][j][1] + xnv[mt * 2]     * e1.x + e1.y;
                rowSum[mt * 2]     += fmaxf(z, 0.f) * e1.z;
                z = acc3[mt][j][2] + xnv[mt * 2 + 1] * e0.x + e0.y;   // row mt*16+8+g
                rowSum[mt * 2 + 1] += fmaxf(z, 0.f) * e0.z;
                z = acc3[mt][j][3] + xnv[mt * 2 + 1] * e1.x + e1.y;
                rowSum[mt * 2 + 1] += fmaxf(z, 0.f) * e1.z;
            }
        }
    }
    __syncthreads();   // all smem consumers done; W2 region free for reduction

    // reduce over the 4 k-threads of each group, then over the two column halves
    float* Pred = (float*)(sm + OFF_W2);   // [2][128]
    #pragma unroll
    for (int i = 0; i < 4; ++i) {
        float v = rowSum[i];
        v += __shfl_xor_sync(0xffffffffu, v, 1);
        v += __shfl_xor_sync(0xffffffffu, v, 2);
        const int rr = bq * 32 + (i & 1) * 8 + (i >> 1) * 16 + g;
        if (tg == 0) Pred[hh * 128 + rr] = v;
    }
    __syncthreads();
    if (tid < 128) {
        const float tot = Pred[tid] + Pred[128 + tid];
        out[(r0 + tid) * NN + n] = fmaxf(tot + b4n, 0.0f);
    }
}

extern "C" void kernel_launch(void* const* d_in, const int* in_sizes, int n_in,
                              void* d_out, int out_size)
{
    const float* x  = (const float*)d_in[0];
    const float* W1 = (const float*)d_in[1];
    const float* W2 = (const float*)d_in[2];
    const float* W3 = (const float*)d_in[3];
    const float* b3 = (const float*)d_in[4];
    const float* W4 = (const float*)d_in[5];
    const float* b4 = (const float*)d_in[6];
    float* out = (float*)d_out;

    cudaFuncSetAttribute(ctp_hmma_kernel,
                         cudaFuncAttributeMaxDynamicSharedMemorySize, SMEM_BYTES);

    dim3 grid(NN, 1024 / TB);   // (64 nodes, 8 batch tiles of 128)
    ctp_hmma_kernel<<<grid, 256, SMEM_BYTES>>>(x, W1, W2, W3, b3, W4, b4, out);
}

// round 9
// speedup vs baseline: 2.5120x; 1.1530x over previous
#include <cuda_runtime.h>
#include <cuda_fp16.h>
#include <cstdint>

#define NN 64
#define HH 512
#define TB 128

#define PIT1  136  // X/A3 tiles: 64 hi | 64 lo | 8 pad   (halves)
#define PITW  72   // W1/W3 chunk: 64 hi | 8 pad
#define PIT2  264  // A2 tile: 128 hi | 128 lo | 8 pad
#define PITW2 136  // W2 chunk: 128 hi | 8 pad

// shared memory byte offsets
#define OFF_XN    0          // 128 floats
#define OFF_EPI   512        // 512 * float4 = 8192
#define OFF_X     8704       // 128*136*2 = 34816  (X hi|lo; later A3)
#define OFF_W13A  43520      // 128*72*2 = 18432  (W1/W3 chunk buf A)
#define OFF_W13B  61952      // buf B
#define OFF_W2A   80384      // 64*136*2 = 17408  (W2 chunk buf A; later reduce buf)
#define OFF_W2B   97792      // buf B
#define OFF_A2    115200     // 128*264*2 = 67584 (relu(H1) chunk, hi|lo)
#define SMEM_BYTES 182784

// ---------------------------------------------------------------- helpers
__device__ __forceinline__ void mma16816(float c[4],
                                         uint32_t a0, uint32_t a1, uint32_t a2, uint32_t a3,
                                         uint32_t b0, uint32_t b1) {
    asm volatile(
        "mma.sync.aligned.m16n8k16.row.col.f32.f16.f16.f32 "
        "{%0,%1,%2,%3}, {%4,%5,%6,%7}, {%8,%9}, {%0,%1,%2,%3};\n"
        : "+f"(c[0]), "+f"(c[1]), "+f"(c[2]), "+f"(c[3])
        : "r"(a0), "r"(a1), "r"(a2), "r"(a3), "r"(b0), "r"(b1));
}

// activations: split into fp16 hi/lo
__device__ __forceinline__ void split_store2(__half* hiP, __half* loP, float a, float b) {
    __half ha = __float2half_rn(a), hb = __float2half_rn(b);
    __half la = __float2half_rn(a - __half2float(ha));
    __half lb = __float2half_rn(b - __half2float(hb));
    *(__half2*)hiP = __halves2half2(ha, hb);
    *(__half2*)loP = __halves2half2(la, lb);
}
__device__ __forceinline__ void split_store4(__half* hiP, __half* loP, float4 v) {
    split_store2(hiP,     loP,     v.x, v.y);
    split_store2(hiP + 2, loP + 2, v.z, v.w);
}
// weights: fp16 hi only, 4 consecutive values as one 8B store
__device__ __forceinline__ void hstore4(__half* p, float4 v) {
    __half2 h01 = __floats2half2_rn(v.x, v.y);
    __half2 h23 = __floats2half2_rn(v.z, v.w);
    *(uint2*)p = make_uint2(*(uint32_t*)&h01, *(uint32_t*)&h23);
}

// K=64 2-pass GEMM: C[32b x 64n] += (A_hi + A_lo) @ W_hi^T
// Row mapping: acc[mt][j][0..1] -> row bq*32+mt*16+g ; [2..3] -> +8
__device__ __forceinline__ void gemm64_2p(const __half* At, const __half* Wt,
                                          int bq, int hh, int g, int tg,
                                          float acc[2][8][4]) {
    #pragma unroll
    for (int ks = 0; ks < 4; ++ks) {
        const int k = ks * 16 + tg * 2;
        uint32_t ah[2][4], al[2][4];
        #pragma unroll
        for (int mt = 0; mt < 2; ++mt) {
            const __half* base = At + (bq * 32 + mt * 16 + g) * PIT1 + k;
            ah[mt][0] = *(const uint32_t*)(base);
            ah[mt][1] = *(const uint32_t*)(base + 8 * PIT1);
            ah[mt][2] = *(const uint32_t*)(base + 8);
            ah[mt][3] = *(const uint32_t*)(base + 8 * PIT1 + 8);
            al[mt][0] = *(const uint32_t*)(base + 64);
            al[mt][1] = *(const uint32_t*)(base + 8 * PIT1 + 64);
            al[mt][2] = *(const uint32_t*)(base + 72);
            al[mt][3] = *(const uint32_t*)(base + 8 * PIT1 + 72);
        }
        #pragma unroll
        for (int j = 0; j < 8; ++j) {
            const __half* bb = Wt + (hh * 64 + j * 8 + g) * PITW + k;
            uint32_t b0 = *(const uint32_t*)(bb);
            uint32_t b1 = *(const uint32_t*)(bb + 8);
            mma16816(acc[0][j], ah[0][0], ah[0][1], ah[0][2], ah[0][3], b0, b1);
            mma16816(acc[0][j], al[0][0], al[0][1], al[0][2], al[0][3], b0, b1);
            mma16816(acc[1][j], ah[1][0], ah[1][1], ah[1][2], ah[1][3], b0, b1);
            mma16816(acc[1][j], al[1][0], al[1][1], al[1][2], al[1][3], b0, b1);
        }
    }
}

// ---------------------------------------------------------------- kernel
__global__ __launch_bounds__(256, 1)
void ctp_hmma_kernel(const float* __restrict__ x,
                     const float* __restrict__ W1,
                     const float* __restrict__ W2,
                     const float* __restrict__ W3,
                     const float* __restrict__ b3,
                     const float* __restrict__ W4,
                     const float* __restrict__ b4,
                     float* __restrict__ out)
{
    extern __shared__ char sm[];
    float*  sXn  = (float*)(sm + OFF_XN);
    float4* sEpi = (float4*)(sm + OFF_EPI);
    __half* Xt   = (__half*)(sm + OFF_X);
    __half* A2t  = (__half*)(sm + OFF_A2);
    __half* w13p[2] = {(__half*)(sm + OFF_W13A), (__half*)(sm + OFF_W13B)};
    __half* w2p[2]  = {(__half*)(sm + OFF_W2A),  (__half*)(sm + OFF_W2B)};

    const int tid  = threadIdx.x;
    const int lane = tid & 31;
    const int wid  = tid >> 5;
    const int g    = lane >> 2;
    const int tg   = lane & 3;
    const int bq   = wid & 3;
    const int hh   = wid >> 2;
    const int n    = blockIdx.x;
    const int r0   = blockIdx.y * TB;

    const float* W1n = W1 + n * (HH * NN);
    const float* W2n = W2 + n * (NN * HH);
    const float* W3n = W3 + n * (HH * 128);

    // per-thread weight-load indices (8 float4 per thread per tile)
    // W1/W3 tile: idx = tid + i*256 ; row = idx>>4, q = (idx&15)*4
    // W2 tile:                       m  = idx>>5, q = (idx&31)*4

    // ---- prologue: X tile (col n zeroed, xn captured) + epilogue vectors ----
    {
        const int row = tid >> 1, hf = tid & 1;
        const float* xr = x + (r0 + row) * NN + hf * 32;
        #pragma unroll
        for (int i = 0; i < 8; ++i) {
            const int c = hf * 32 + i * 4;
            float4 v = *(const float4*)(xr + i * 4);
            if (n >= c && n < c + 4) {
                float vv[4] = {v.x, v.y, v.z, v.w};
                sXn[row] = vv[n - c];
                vv[n - c] = 0.0f;
                v = make_float4(vv[0], vv[1], vv[2], vv[3]);
            }
            split_store4(Xt + row * PIT1 + c, Xt + row * PIT1 + 64 + c, v);
        }
    }
    // chunk-0 weights straight to smem
    #pragma unroll
    for (int i = 0; i < 8; ++i) {
        const int idx = tid + i * 256;
        const int row = idx >> 4, q = (idx & 15) * 4;
        hstore4(w13p[0] + row * PITW + q, *(const float4*)(W1n + row * NN + q));
        const int m = idx >> 5, q2 = (idx & 31) * 4;
        hstore4(w2p[0] + m * PITW2 + q2, *(const float4*)(W2n + m * HH + q2));
    }
    for (int idx = tid; idx < HH; idx += 256)
        sEpi[idx] = make_float4(W3n[idx * 128 + 64 + n],
                                b3[n * HH + idx],
                                W4[n * HH + idx], 0.0f);
    const float b4n = b4[n];
    __syncthreads();

    float acc2[2][4][4] = {};   // D2 [128b x 64m] warp slice, persistent

    // =================== Stages 1+2 over 4 H-chunks of 128 ===================
    #pragma unroll
    for (int hc = 0; hc < 4; ++hc) {
        const int cur = hc & 1, nxt = cur ^ 1;

        // prefetch next W1 chunk (or W3 chunk 0 on last iter) into registers
        float4 r1[8];
        {
            const float* src = (hc < 3) ? (W1n + (hc + 1) * 128 * NN) : W3n;
            const int   strd = (hc < 3) ? NN : 128;
            #pragma unroll
            for (int i = 0; i < 8; ++i) {
                const int idx = tid + i * 256;
                r1[i] = *(const float4*)(src + (idx >> 4) * strd + (idx & 15) * 4);
            }
        }

        // stage 1: D1 chunk [128b x 128h] = X @ W1c^T  (hides r1 LDGs)
        float acc1[2][8][4] = {};
        gemm64_2p(Xt, w13p[cur], bq, hh, g, tg, acc1);

        // store prefetched weights into the other W13 buffer
        #pragma unroll
        for (int i = 0; i < 8; ++i) {
            const int idx = tid + i * 256;
            hstore4(w13p[nxt] + (idx >> 4) * PITW + (idx & 15) * 4, r1[i]);
        }

        // prefetch next W2 chunk into registers
        float4 r2[8];
        if (hc < 3) {
            #pragma unroll
            for (int i = 0; i < 8; ++i) {
                const int idx = tid + i * 256;
                r2[i] = *(const float4*)(W2n + (idx >> 5) * HH + (hc + 1) * 128 + (idx & 31) * 4);
            }
        }

        __syncthreads();   // (a) prev MMA2 done -> A2 free; W13[nxt] stored

        // relu + split-store into A2 (hi at c, lo at 128+c)
        #pragma unroll
        for (int mt = 0; mt < 2; ++mt) {
            const int r = bq * 32 + mt * 16 + g;
            #pragma unroll
            for (int j = 0; j < 8; ++j) {
                const int c = hh * 64 + j * 8 + tg * 2;
                split_store2(A2t + r * PIT2 + c,       A2t + r * PIT2 + 128 + c,
                             fmaxf(acc1[mt][j][0], 0.f), fmaxf(acc1[mt][j][1], 0.f));
                split_store2(A2t + (r + 8) * PIT2 + c, A2t + (r + 8) * PIT2 + 128 + c,
                             fmaxf(acc1[mt][j][2], 0.f), fmaxf(acc1[mt][j][3], 0.f));
            }
        }
        __syncthreads();   // (b) A2 visible

        // stage 2 partial: D2 += A2chunk @ W2chunk^T (K=128, 2 passes; hides r2 store)
        #pragma unroll
        for (int ks = 0; ks < 8; ++ks) {
            const int k = ks * 16 + tg * 2;
            uint32_t ah[2][4], al[2][4];
            #pragma unroll
            for (int mt = 0; mt < 2; ++mt) {
                const __half* base = A2t + (bq * 32 + mt * 16 + g) * PIT2 + k;
                ah[mt][0] = *(const uint32_t*)(base);
                ah[mt][1] = *(const uint32_t*)(base + 8 * PIT2);
                ah[mt][2] = *(const uint32_t*)(base + 8);
                ah[mt][3] = *(const uint32_t*)(base + 8 * PIT2 + 8);
                al[mt][0] = *(const uint32_t*)(base + 128);
                al[mt][1] = *(const uint32_t*)(base + 8 * PIT2 + 128);
                al[mt][2] = *(const uint32_t*)(base + 136);
                al[mt][3] = *(const uint32_t*)(base + 8 * PIT2 + 136);
            }
            #pragma unroll
            for (int j = 0; j < 4; ++j) {
                const __half* bb = w2p[cur] + (hh * 32 + j * 8 + g) * PITW2 + k;
                uint32_t b0 = *(const uint32_t*)(bb);
                uint32_t b1 = *(const uint32_t*)(bb + 8);
                mma16816(acc2[0][j], ah[0][0], ah[0][1], ah[0][2], ah[0][3], b0, b1);
                mma16816(acc2[0][j], al[0][0], al[0][1], al[0][2], al[0][3], b0, b1);
                mma16816(acc2[1][j], ah[1][0], ah[1][1], ah[1][2], ah[1][3], b0, b1);
                mma16816(acc2[1][j], al[1][0], al[1][1], al[1][2], al[1][3], b0, b1);
            }
        }

        // store prefetched W2 into the other buffer
        if (hc < 3) {
            #pragma unroll
            for (int i = 0; i < 8; ++i) {
                const int idx = tid + i * 256;
                hstore4(w2p[nxt] + (idx >> 5) * PITW2 + (idx & 31) * 4, r2[i]);
            }
        }
    }

    // ---- A3 = relu(D2) -> hi/lo into X buffer (X dead after stage 1) ----
    #pragma unroll
    for (int mt = 0; mt < 2; ++mt) {
        const int r = bq * 32 + mt * 16 + g;
        #pragma unroll
        for (int j = 0; j < 4; ++j) {
            const int c = hh * 32 + j * 8 + tg * 2;
            split_store2(Xt + r * PIT1 + c,       Xt + r * PIT1 + 64 + c,
                         fmaxf(acc2[mt][j][0], 0.f), fmaxf(acc2[mt][j][1], 0.f));
            split_store2(Xt + (r + 8) * PIT1 + c, Xt + (r + 8) * PIT1 + 64 + c,
                         fmaxf(acc2[mt][j][2], 0.f), fmaxf(acc2[mt][j][3], 0.f));
        }
    }
    __syncthreads();   // A3 visible; W13 buf0 holds W3 chunk 0 (stored in hc=3)

    // xn per accumulator row group: rows {g, 8+g, 16+g, 24+g}
    float xnv[4];
    #pragma unroll
    for (int i = 0; i < 4; ++i) xnv[i] = sXn[bq * 32 + i * 8 + g];

    // =================== Stage 3 over 4 H-chunks, fused epilogue ===================
    float rowSum[4] = {};
    #pragma unroll
    for (int hc = 0; hc < 4; ++hc) {
        const int cur = hc & 1, nxt = cur ^ 1;

        // prefetch next W3 chunk into registers
        float4 r3[8];
        if (hc < 3) {
            const float* src = W3n + (hc + 1) * 128 * 128;
            #pragma unroll
            for (int i = 0; i < 8; ++i) {
                const int idx = tid + i * 256;
                r3[i] = *(const float4*)(src + (idx >> 4) * 128 + (idx & 15) * 4);
            }
        }

        float acc3[2][8][4] = {};
        gemm64_2p(Xt, w13p[cur], bq, hh, g, tg, acc3);

        // z = d3 + xn*w3col + b3 ; rowSum += relu(z)*w4
        #pragma unroll
        for (int j = 0; j < 8; ++j) {
            const int colb = hc * 128 + hh * 64 + j * 8 + tg * 2;
            const float4 e0 = sEpi[colb];
            const float4 e1 = sEpi[colb + 1];
            #pragma unroll
            for (int mt = 0; mt < 2; ++mt) {
                float z;
                z = acc3[mt][j][0] + xnv[mt * 2]     * e0.x + e0.y;   // row mt*16+g
                rowSum[mt * 2]     += fmaxf(z, 0.f) * e0.z;
                z = acc3[mt][j][1] + xnv[mt * 2]     * e1.x + e1.y;
                rowSum[mt * 2]     += fmaxf(z, 0.f) * e1.z;
                z = acc3[mt][j][2] + xnv[mt * 2 + 1] * e0.x + e0.y;   // row mt*16+8+g
                rowSum[mt * 2 + 1] += fmaxf(z, 0.f) * e0.z;
                z = acc3[mt][j][3] + xnv[mt * 2 + 1] * e1.x + e1.y;
                rowSum[mt * 2 + 1] += fmaxf(z, 0.f) * e1.z;
            }
        }

        if (hc < 3) {
            #pragma unroll
            for (int i = 0; i < 8; ++i) {
                const int idx = tid + i * 256;
                hstore4(w13p[nxt] + (idx >> 4) * PITW + (idx & 15) * 4, r3[i]);
            }
        }
        __syncthreads();   // W13[nxt] stored + this iter's readers done
    }

    // reduce over the 4 k-threads of each group, then over the two column halves
    float* Pred = (float*)(sm + OFF_W2A);   // [2][128]
    #pragma unroll
    for (int i = 0; i < 4; ++i) {
        float v = rowSum[i];
        v += __shfl_xor_sync(0xffffffffu, v, 1);
        v += __shfl_xor_sync(0xffffffffu, v, 2);
        const int rr = bq * 32 + (i & 1) * 8 + (i >> 1) * 16 + g;
        if (tg == 0) Pred[hh * 128 + rr] = v;
    }
    __syncthreads();
    if (tid < 128) {
        const float tot = Pred[tid] + Pred[128 + tid];
        out[(r0 + tid) * NN + n] = fmaxf(tot + b4n, 0.0f);
    }
}

extern "C" void kernel_launch(void* const* d_in, const int* in_sizes, int n_in,
                              void* d_out, int out_size)
{
    const float* x  = (const float*)d_in[0];
    const float* W1 = (const float*)d_in[1];
    const float* W2 = (const float*)d_in[2];
    const float* W3 = (const float*)d_in[3];
    const float* b3 = (const float*)d_in[4];
    const float* W4 = (const float*)d_in[5];
    const float* b4 = (const float*)d_in[6];
    float* out = (float*)d_out;

    cudaFuncSetAttribute(ctp_hmma_kernel,
                         cudaFuncAttributeMaxDynamicSharedMemorySize, SMEM_BYTES);

    dim3 grid(NN, 1024 / TB);   // (64 nodes, 8 batch tiles of 128)
    ctp_hmma_kernel<<<grid, 256, SMEM_BYTES>>>(x, W1, W2, W3, b3, W4, b4, out);
}

// round 10
// speedup vs baseline: 3.3902x; 1.3496x over previous
#include <cuda_runtime.h>
#include <cuda_fp16.h>
#include <cstdint>

#define NN 64
#define HH 512
#define TB 128
#define NT 512     // threads per CTA (16 warps)

#define PITW  72   // pitch (halves) for [*][64k] fp16 tiles: X/A3, W1/W3 chunks
#define PIT2  136  // pitch (halves) for [*][128k] fp16 tiles: A2, W2 chunk

// shared memory byte offsets
#define OFF_XN    0          // 128 floats
#define OFF_EPI   512        // 512 * float4 = 8192
#define OFF_X     8704       // 128*72*2 = 18432   (X; later A3)
#define OFF_W13A  27136      // W1/W3 chunk buf A
#define OFF_W13B  45568      // buf B
#define OFF_W2A   64000      // 64*136*2 = 17408   (W2 buf A; later reduce buf)
#define OFF_W2B   81408      // buf B
#define OFF_A2    98816      // 128*136*2 = 34816  (relu(H1) chunk)
#define SMEM_BYTES 133632

// ---------------------------------------------------------------- helpers
__device__ __forceinline__ void mma16816(float c[4],
                                         uint32_t a0, uint32_t a1, uint32_t a2, uint32_t a3,
                                         uint32_t b0, uint32_t b1) {
    asm volatile(
        "mma.sync.aligned.m16n8k16.row.col.f32.f16.f16.f32 "
        "{%0,%1,%2,%3}, {%4,%5,%6,%7}, {%8,%9}, {%0,%1,%2,%3};\n"
        : "+f"(c[0]), "+f"(c[1]), "+f"(c[2]), "+f"(c[3])
        : "r"(a0), "r"(a1), "r"(a2), "r"(a3), "r"(b0), "r"(b1));
}
__device__ __forceinline__ void hstore2(__half* p, float a, float b) {
    *(__half2*)p = __floats2half2_rn(a, b);
}
__device__ __forceinline__ void hstore4(__half* p, float4 v) {
    __half2 h01 = __floats2half2_rn(v.x, v.y);
    __half2 h23 = __floats2half2_rn(v.z, v.w);
    *(uint2*)p = make_uint2(*(uint32_t*)&h01, *(uint32_t*)&h23);
}

// K=64 fp16 GEMM: C[32b x 32n] += A @ W^T   (A,W pitch PITW)
// Row mapping: acc[mt][j][0..1] -> row bq*32+mt*16+g ; [2..3] -> +8
// Col mapping: col = cc*32 + j*8 + tg*2 (+1)
__device__ __forceinline__ void gemm64(const __half* At, const __half* Wt,
                                       int bq, int cc, int g, int tg,
                                       float acc[2][4][4]) {
    #pragma unroll
    for (int ks = 0; ks < 4; ++ks) {
        const int k = ks * 16 + tg * 2;
        uint32_t a[2][4];
        #pragma unroll
        for (int mt = 0; mt < 2; ++mt) {
            const __half* base = At + (bq * 32 + mt * 16 + g) * PITW + k;
            a[mt][0] = *(const uint32_t*)(base);
            a[mt][1] = *(const uint32_t*)(base + 8 * PITW);
            a[mt][2] = *(const uint32_t*)(base + 8);
            a[mt][3] = *(const uint32_t*)(base + 8 * PITW + 8);
        }
        #pragma unroll
        for (int j = 0; j < 4; ++j) {
            const __half* bb = Wt + (cc * 32 + j * 8 + g) * PITW + k;
            uint32_t b0 = *(const uint32_t*)(bb);
            uint32_t b1 = *(const uint32_t*)(bb + 8);
            mma16816(acc[0][j], a[0][0], a[0][1], a[0][2], a[0][3], b0, b1);
            mma16816(acc[1][j], a[1][0], a[1][1], a[1][2], a[1][3], b0, b1);
        }
    }
}

// ---------------------------------------------------------------- kernel
__global__ __launch_bounds__(NT, 1)
void ctp_hmma_kernel(const float* __restrict__ x,
                     const float* __restrict__ W1,
                     const float* __restrict__ W2,
                     const float* __restrict__ W3,
                     const float* __restrict__ b3,
                     const float* __restrict__ W4,
                     const float* __restrict__ b4,
                     float* __restrict__ out)
{
    extern __shared__ char sm[];
    float*  sXn  = (float*)(sm + OFF_XN);
    float4* sEpi = (float4*)(sm + OFF_EPI);
    __half* Xt   = (__half*)(sm + OFF_X);
    __half* A2t  = (__half*)(sm + OFF_A2);
    __half* w13p[2] = {(__half*)(sm + OFF_W13A), (__half*)(sm + OFF_W13B)};
    __half* w2p[2]  = {(__half*)(sm + OFF_W2A),  (__half*)(sm + OFF_W2B)};

    const int tid  = threadIdx.x;
    const int lane = tid & 31;
    const int wid  = tid >> 5;          // 0..15
    const int g    = lane >> 2;
    const int tg   = lane & 3;
    const int bq   = wid & 3;           // 32-row batch group
    const int cc   = wid >> 2;          // column quarter (0..3)
    const int n    = blockIdx.x;
    const int r0   = blockIdx.y * TB;

    const float* W1n = W1 + n * (HH * NN);
    const float* W2n = W2 + n * (NN * HH);
    const float* W3n = W3 + n * (HH * 128);

    // ---- prologue: X tile (col n zeroed, xn captured), chunk-0 weights, epi ----
    {
        const int row = tid >> 2;
        const int q0  = (tid & 3) * 16;
        const float* xr = x + (r0 + row) * NN + q0;
        #pragma unroll
        for (int i = 0; i < 4; ++i) {
            const int c = q0 + i * 4;
            float4 v = *(const float4*)(xr + i * 4);
            if (n >= c && n < c + 4) {
                float vv[4] = {v.x, v.y, v.z, v.w};
                sXn[row] = vv[n - c];
                vv[n - c] = 0.0f;
                v = make_float4(vv[0], vv[1], vv[2], vv[3]);
            }
            hstore4(Xt + row * PITW + c, v);
        }
    }
    #pragma unroll
    for (int i = 0; i < 4; ++i) {
        const int idx = tid + i * NT;
        const int row = idx >> 4, q = (idx & 15) * 4;
        hstore4(w13p[0] + row * PITW + q, *(const float4*)(W1n + row * NN + q));
        const int m = idx >> 5, q2 = (idx & 31) * 4;
        hstore4(w2p[0] + m * PIT2 + q2, *(const float4*)(W2n + m * HH + q2));
    }
    sEpi[tid] = make_float4(W3n[tid * 128 + 64 + n],
                            b3[n * HH + tid],
                            W4[n * HH + tid], 0.0f);
    const float b4n = b4[n];
    __syncthreads();

    float acc2[2][2][4] = {};   // D2 [128b x 64m] warp slice (32b x 16m), persistent

    // =================== Stages 1+2 over 4 H-chunks of 128 ===================
    #pragma unroll
    for (int hc = 0; hc < 4; ++hc) {
        const int cur = hc & 1, nxt = cur ^ 1;

        // prefetch next W1 chunk (or W3 chunk 0 on last iter) into registers
        float4 r1[4];
        {
            const float* src = (hc < 3) ? (W1n + (hc + 1) * 128 * NN) : W3n;
            const int   strd = (hc < 3) ? NN : 128;
            #pragma unroll
            for (int i = 0; i < 4; ++i) {
                const int idx = tid + i * NT;
                r1[i] = *(const float4*)(src + (idx >> 4) * strd + (idx & 15) * 4);
            }
        }

        // stage 1: D1 chunk [128b x 128h] = X @ W1c^T (hides r1 LDGs)
        float acc1[2][4][4] = {};
        gemm64(Xt, w13p[cur], bq, cc, g, tg, acc1);

        // store prefetched weights into the other W13 buffer
        #pragma unroll
        for (int i = 0; i < 4; ++i) {
            const int idx = tid + i * NT;
            hstore4(w13p[nxt] + (idx >> 4) * PITW + (idx & 15) * 4, r1[i]);
        }

        // prefetch next W2 chunk into registers
        float4 r2[4];
        if (hc < 3) {
            #pragma unroll
            for (int i = 0; i < 4; ++i) {
                const int idx = tid + i * NT;
                r2[i] = *(const float4*)(W2n + (idx >> 5) * HH + (hc + 1) * 128 + (idx & 31) * 4);
            }
        }

        __syncthreads();   // (a) prev MMA2 readers done -> A2 free; W13[nxt] stored

        // relu + fp16 store into A2
        #pragma unroll
        for (int mt = 0; mt < 2; ++mt) {
            const int r = bq * 32 + mt * 16 + g;
            #pragma unroll
            for (int j = 0; j < 4; ++j) {
                const int c = cc * 32 + j * 8 + tg * 2;
                hstore2(A2t + r * PIT2 + c,
                        fmaxf(acc1[mt][j][0], 0.f), fmaxf(acc1[mt][j][1], 0.f));
                hstore2(A2t + (r + 8) * PIT2 + c,
                        fmaxf(acc1[mt][j][2], 0.f), fmaxf(acc1[mt][j][3], 0.f));
            }
        }
        __syncthreads();   // (b) A2 visible

        // stage 2 partial: D2 += A2chunk @ W2chunk^T (K=128)
        #pragma unroll
        for (int ks = 0; ks < 8; ++ks) {
            const int k = ks * 16 + tg * 2;
            uint32_t a[2][4];
            #pragma unroll
            for (int mt = 0; mt < 2; ++mt) {
                const __half* base = A2t + (bq * 32 + mt * 16 + g) * PIT2 + k;
                a[mt][0] = *(const uint32_t*)(base);
                a[mt][1] = *(const uint32_t*)(base + 8 * PIT2);
                a[mt][2] = *(const uint32_t*)(base + 8);
                a[mt][3] = *(const uint32_t*)(base + 8 * PIT2 + 8);
            }
            #pragma unroll
            for (int j = 0; j < 2; ++j) {
                const __half* bb = w2p[cur] + (cc * 16 + j * 8 + g) * PIT2 + k;
                uint32_t b0 = *(const uint32_t*)(bb);
                uint32_t b1 = *(const uint32_t*)(bb + 8);
                mma16816(acc2[0][j], a[0][0], a[0][1], a[0][2], a[0][3], b0, b1);
                mma16816(acc2[1][j], a[1][0], a[1][1], a[1][2], a[1][3], b0, b1);
            }
        }

        // store prefetched W2 into the other buffer
        if (hc < 3) {
            #pragma unroll
            for (int i = 0; i < 4; ++i) {
                const int idx = tid + i * NT;
                hstore4(w2p[nxt] + (idx >> 5) * PIT2 + (idx & 31) * 4, r2[i]);
            }
        }
    }

    // ---- A3 = relu(D2) -> fp16 into X buffer (X dead after stage 1) ----
    // warp slice cols: cc*16 + j*8 + tg*2
    #pragma unroll
    for (int mt = 0; mt < 2; ++mt) {
        const int r = bq * 32 + mt * 16 + g;
        #pragma unroll
        for (int j = 0; j < 2; ++j) {
            const int c = cc * 16 + j * 8 + tg * 2;
            hstore2(Xt + r * PITW + c,
                    fmaxf(acc2[mt][j][0], 0.f), fmaxf(acc2[mt][j][1], 0.f));
            hstore2(Xt + (r + 8) * PITW + c,
                    fmaxf(acc2[mt][j][2], 0.f), fmaxf(acc2[mt][j][3], 0.f));
        }
    }
    __syncthreads();   // A3 visible; w13p[0] holds W3 chunk 0 (stored at hc=3)

    // xn per accumulator row group: rows {g, 8+g, 16+g, 24+g}
    float xnv[4];
    #pragma unroll
    for (int i = 0; i < 4; ++i) xnv[i] = sXn[bq * 32 + i * 8 + g];

    // =================== Stage 3 over 4 H-chunks, fused epilogue ===================
    float rowSum[4] = {};
    #pragma unroll
    for (int hc = 0; hc < 4; ++hc) {
        const int cur = hc & 1, nxt = cur ^ 1;

        float4 r3[4];
        if (hc < 3) {
            const float* src = W3n + (hc + 1) * 128 * 128;
            #pragma unroll
            for (int i = 0; i < 4; ++i) {
                const int idx = tid + i * NT;
                r3[i] = *(const float4*)(src + (idx >> 4) * 128 + (idx & 15) * 4);
            }
        }

        float acc3[2][4][4] = {};
        gemm64(Xt, w13p[cur], bq, cc, g, tg, acc3);

        // z = d3 + xn*w3col + b3 ; rowSum += relu(z)*w4
        #pragma unroll
        for (int j = 0; j < 4; ++j) {
            const int colb = hc * 128 + cc * 32 + j * 8 + tg * 2;
            const float4 e0 = sEpi[colb];
            const float4 e1 = sEpi[colb + 1];
            #pragma unroll
            for (int mt = 0; mt < 2; ++mt) {
                float z;
                z = acc3[mt][j][0] + xnv[mt * 2]     * e0.x + e0.y;   // row mt*16+g
                rowSum[mt * 2]     += fmaxf(z, 0.f) * e0.z;
                z = acc3[mt][j][1] + xnv[mt * 2]     * e1.x + e1.y;
                rowSum[mt * 2]     += fmaxf(z, 0.f) * e1.z;
                z = acc3[mt][j][2] + xnv[mt * 2 + 1] * e0.x + e0.y;   // row mt*16+8+g
                rowSum[mt * 2 + 1] += fmaxf(z, 0.f) * e0.z;
                z = acc3[mt][j][3] + xnv[mt * 2 + 1] * e1.x + e1.y;
                rowSum[mt * 2 + 1] += fmaxf(z, 0.f) * e1.z;
            }
        }

        if (hc < 3) {
            #pragma unroll
            for (int i = 0; i < 4; ++i) {
                const int idx = tid + i * NT;
                hstore4(w13p[nxt] + (idx >> 4) * PITW + (idx & 15) * 4, r3[i]);
            }
        }
        __syncthreads();   // W13[nxt] stored + this iter's readers done
    }

    // reduce over the 4 k-threads of each group, then over the 4 column quarters
    float* Pred = (float*)(sm + OFF_W2A);   // [4][128]
    #pragma unroll
    for (int i = 0; i < 4; ++i) {
        float v = rowSum[i];
        v += __shfl_xor_sync(0xffffffffu, v, 1);
        v += __shfl_xor_sync(0xffffffffu, v, 2);
        const int rr = bq * 32 + (i & 1) * 8 + (i >> 1) * 16 + g;
        if (tg == 0) Pred[cc * 128 + rr] = v;
    }
    __syncthreads();
    if (tid < 128) {
        const float tot = Pred[tid] + Pred[128 + tid] + Pred[256 + tid] + Pred[384 + tid];
        out[(r0 + tid) * NN + n] = fmaxf(tot + b4n, 0.0f);
    }
}

extern "C" void kernel_launch(void* const* d_in, const int* in_sizes, int n_in,
                              void* d_out, int out_size)
{
    const float* x  = (const float*)d_in[0];
    const float* W1 = (const float*)d_in[1];
    const float* W2 = (const float*)d_in[2];
    const float* W3 = (const float*)d_in[3];
    const float* b3 = (const float*)d_in[4];
    const float* W4 = (const float*)d_in[5];
    const float* b4 = (const float*)d_in[6];
    float* out = (float*)d_out;

    cudaFuncSetAttribute(ctp_hmma_kernel,
                         cudaFuncAttributeMaxDynamicSharedMemorySize, SMEM_BYTES);

    dim3 grid(NN, 1024 / TB);   // (64 nodes, 8 batch tiles of 128)
    ctp_hmma_kernel<<<grid, NT, SMEM_BYTES>>>(x, W1, W2, W3, b3, W4, b4, out);
}

// round 11
// speedup vs baseline: 3.5915x; 1.0594x over previous
#include <cuda_runtime.h>
#include <cuda_fp16.h>
#include <cstdint>

#define NN 64
#define HH 512
#define TB 128
#define NT 512     // threads per CTA (16 warps)

#define PITW  72   // pitch (halves) for [*][64k] fp16 tiles: X/A3, W1/W3 chunks
#define PIT2  136  // pitch (halves) for [*][128k] fp16 tiles: A2, W2 chunk

// shared memory byte offsets (all 16B-aligned; pitches 144B/272B ≡ 4 banks mod 32
// -> ldmatrix/stmatrix conflict-free)
#define OFF_XN    0          // 128 floats
#define OFF_EPI   512        // 512 * float4 = 8192
#define OFF_X     8704       // 128*72*2 = 18432   (X; later A3)
#define OFF_W13A  27136      // W1/W3 chunk buf A
#define OFF_W13B  45568      // buf B
#define OFF_W2A   64000      // 64*136*2 = 17408   (W2 buf A; later reduce buf)
#define OFF_W2B   81408      // buf B
#define OFF_A2    98816      // 128*136*2 = 34816  (relu(H1) chunk)
#define SMEM_BYTES 133632

// ---------------------------------------------------------------- helpers
__device__ __forceinline__ uint32_t smem_u32(const void* p) {
    uint32_t a;
    asm("{ .reg .u64 t; cvta.to.shared.u64 t, %1; cvt.u32.u64 %0, t; }"
        : "=r"(a) : "l"(p));
    return a;
}
__device__ __forceinline__ void mma16816(float c[4],
                                         uint32_t a0, uint32_t a1, uint32_t a2, uint32_t a3,
                                         uint32_t b0, uint32_t b1) {
    asm volatile(
        "mma.sync.aligned.m16n8k16.row.col.f32.f16.f16.f32 "
        "{%0,%1,%2,%3}, {%4,%5,%6,%7}, {%8,%9}, {%0,%1,%2,%3};\n"
        : "+f"(c[0]), "+f"(c[1]), "+f"(c[2]), "+f"(c[3])
        : "r"(a0), "r"(a1), "r"(a2), "r"(a3), "r"(b0), "r"(b1));
}
__device__ __forceinline__ void ldm4(uint32_t r[4], uint32_t a) {
    asm volatile("ldmatrix.sync.aligned.m8n8.x4.shared.b16 {%0,%1,%2,%3}, [%4];"
                 : "=r"(r[0]), "=r"(r[1]), "=r"(r[2]), "=r"(r[3]) : "r"(a));
}
__device__ __forceinline__ void stm4(uint32_t a, uint32_t r0, uint32_t r1,
                                     uint32_t r2, uint32_t r3) {
    asm volatile("stmatrix.sync.aligned.m8n8.x4.shared.b16 [%0], {%1,%2,%3,%4};"
                 :: "r"(a), "r"(r0), "r"(r1), "r"(r2), "r"(r3) : "memory");
}
__device__ __forceinline__ uint32_t relu_h2(float a, float b) {
    __half2 h = __floats2half2_rn(fmaxf(a, 0.f), fmaxf(b, 0.f));
    return *(uint32_t*)&h;
}
__device__ __forceinline__ void hstore4(__half* p, float4 v) {
    __half2 h01 = __floats2half2_rn(v.x, v.y);
    __half2 h23 = __floats2half2_rn(v.z, v.w);
    *(uint2*)p = make_uint2(*(uint32_t*)&h01, *(uint32_t*)&h23);
}

// K=64 fp16 GEMM via ldmatrix: C[32b x 32n] += A @ W^T
// aB0/aB1: per-thread ldmatrix base for A tiles mt=0/1 (pitch PITW)
// wB0/wB1: per-thread ldmatrix base for B j-pairs 0/1
__device__ __forceinline__ void gemm64_lm(uint32_t aB0, uint32_t aB1,
                                          uint32_t wB0, uint32_t wB1,
                                          float acc[2][4][4]) {
    #pragma unroll
    for (int ks = 0; ks < 4; ++ks) {
        uint32_t a0[4], a1[4], b0[4], b1[4];
        ldm4(a0, aB0 + ks * 32);
        ldm4(a1, aB1 + ks * 32);
        ldm4(b0, wB0 + ks * 32);
        ldm4(b1, wB1 + ks * 32);
        mma16816(acc[0][0], a0[0], a0[1], a0[2], a0[3], b0[0], b0[1]);
        mma16816(acc[0][1], a0[0], a0[1], a0[2], a0[3], b0[2], b0[3]);
        mma16816(acc[0][2], a0[0], a0[1], a0[2], a0[3], b1[0], b1[1]);
        mma16816(acc[0][3], a0[0], a0[1], a0[2], a0[3], b1[2], b1[3]);
        mma16816(acc[1][0], a1[0], a1[1], a1[2], a1[3], b0[0], b0[1]);
        mma16816(acc[1][1], a1[0], a1[1], a1[2], a1[3], b0[2], b0[3]);
        mma16816(acc[1][2], a1[0], a1[1], a1[2], a1[3], b1[0], b1[1]);
        mma16816(acc[1][3], a1[0], a1[1], a1[2], a1[3], b1[2], b1[3]);
    }
}

// ---------------------------------------------------------------- kernel
__global__ __launch_bounds__(NT, 1)
void ctp_hmma_kernel(const float* __restrict__ x,
                     const float* __restrict__ W1,
                     const float* __restrict__ W2,
                     const float* __restrict__ W3,
                     const float* __restrict__ b3,
                     const float* __restrict__ W4,
                     const float* __restrict__ b4,
                     float* __restrict__ out)
{
    extern __shared__ char sm[];
    float*  sXn  = (float*)(sm + OFF_XN);
    float4* sEpi = (float4*)(sm + OFF_EPI);
    __half* Xt   = (__half*)(sm + OFF_X);
    __half* w13p[2] = {(__half*)(sm + OFF_W13A), (__half*)(sm + OFF_W13B)};
    __half* w2p[2]  = {(__half*)(sm + OFF_W2A),  (__half*)(sm + OFF_W2B)};

    const uint32_t uX   = smem_u32(sm + OFF_X);
    const uint32_t uA2  = smem_u32(sm + OFF_A2);
    const uint32_t uW13[2] = {smem_u32(sm + OFF_W13A), smem_u32(sm + OFF_W13B)};
    const uint32_t uW2[2]  = {smem_u32(sm + OFF_W2A),  smem_u32(sm + OFF_W2B)};

    const int tid  = threadIdx.x;
    const int lane = tid & 31;
    const int wid  = tid >> 5;          // 0..15
    const int g    = lane >> 2;
    const int tg   = lane & 3;
    const int bq   = wid & 3;           // 32-row batch group
    const int cc   = wid >> 2;          // column quarter (0..3)
    const int n    = blockIdx.x;
    const int r0   = blockIdx.y * TB;

    // ldmatrix per-thread offsets
    const int arow  = bq * 32 + (lane & 15);       // A row for this lane
    const int acol  = (lane >> 4) * 8;             // k-half select
    const int brow  = (lane & 7) + ((lane >> 4) << 3);   // B row-within-pair
    const int bcol  = ((lane >> 3) & 1) * 8;
    // A bases (X/A3 tile, pitch PITW)
    const uint32_t aX0 = uX + (arow * PITW + acol) * 2;
    const uint32_t aX1 = aX0 + 16 * PITW * 2;
    // A bases (A2 tile, pitch PIT2)
    const uint32_t aA0 = uA2 + (arow * PIT2 + acol) * 2;
    const uint32_t aA1 = aA0 + 16 * PIT2 * 2;
    // B offsets (relative; add buffer base)
    const uint32_t w13off0 = ((cc * 32 + brow) * PITW + bcol) * 2;
    const uint32_t w13off1 = w13off0 + 16 * PITW * 2;
    const uint32_t w2off   = ((cc * 16 + brow) * PIT2 + bcol) * 2;
    // stmatrix bases
    const int srow = lane & 15;
    const int scol = (lane >> 4) * 8;
    const uint32_t stA2 = uA2 + ((bq * 32 + srow) * PIT2 + cc * 32 + scol) * 2;
    const uint32_t stX  = uX  + ((bq * 32 + srow) * PITW + cc * 16 + scol) * 2;

    const float* W1n = W1 + n * (HH * NN);
    const float* W2n = W2 + n * (NN * HH);
    const float* W3n = W3 + n * (HH * 128);

    // ---- prologue: X tile (col n zeroed, xn captured), chunk-0 weights, epi ----
    {
        const int row = tid >> 2;
        const int q0  = (tid & 3) * 16;
        const float* xr = x + (r0 + row) * NN + q0;
        #pragma unroll
        for (int i = 0; i < 4; ++i) {
            const int c = q0 + i * 4;
            float4 v = *(const float4*)(xr + i * 4);
            if (n >= c && n < c + 4) {
                float vv[4] = {v.x, v.y, v.z, v.w};
                sXn[row] = vv[n - c];
                vv[n - c] = 0.0f;
                v = make_float4(vv[0], vv[1], vv[2], vv[3]);
            }
            hstore4(Xt + row * PITW + c, v);
        }
    }
    #pragma unroll
    for (int i = 0; i < 4; ++i) {
        const int idx = tid + i * NT;
        const int row = idx >> 4, q = (idx & 15) * 4;
        hstore4(w13p[0] + row * PITW + q, *(const float4*)(W1n + row * NN + q));
        const int m = idx >> 5, q2 = (idx & 31) * 4;
        hstore4(w2p[0] + m * PIT2 + q2, *(const float4*)(W2n + m * HH + q2));
    }
    sEpi[tid] = make_float4(W3n[tid * 128 + 64 + n],
                            b3[n * HH + tid],
                            W4[n * HH + tid], 0.0f);
    const float b4n = b4[n];
    __syncthreads();

    float acc2[2][2][4] = {};   // D2 [128b x 64m] warp slice (32b x 16m), persistent

    // =================== Stages 1+2 over 4 H-chunks of 128 ===================
    #pragma unroll
    for (int hc = 0; hc < 4; ++hc) {
        const int cur = hc & 1, nxt = cur ^ 1;

        // prefetch next W1 chunk (or W3 chunk 0 on last iter) into registers
        float4 r1[4];
        {
            const float* src = (hc < 3) ? (W1n + (hc + 1) * 128 * NN) : W3n;
            const int   strd = (hc < 3) ? NN : 128;
            #pragma unroll
            for (int i = 0; i < 4; ++i) {
                const int idx = tid + i * NT;
                r1[i] = *(const float4*)(src + (idx >> 4) * strd + (idx & 15) * 4);
            }
        }

        // stage 1: D1 chunk [128b x 128h] = X @ W1c^T (hides r1 LDGs)
        float acc1[2][4][4] = {};
        gemm64_lm(aX0, aX1, uW13[cur] + w13off0, uW13[cur] + w13off1, acc1);

        // store prefetched weights into the other W13 buffer
        #pragma unroll
        for (int i = 0; i < 4; ++i) {
            const int idx = tid + i * NT;
            hstore4(w13p[nxt] + (idx >> 4) * PITW + (idx & 15) * 4, r1[i]);
        }

        // prefetch next W2 chunk into registers
        float4 r2[4];
        if (hc < 3) {
            #pragma unroll
            for (int i = 0; i < 4; ++i) {
                const int idx = tid + i * NT;
                r2[i] = *(const float4*)(W2n + (idx >> 5) * HH + (hc + 1) * 128 + (idx & 31) * 4);
            }
        }

        __syncthreads();   // (a) prev MMA2 readers done -> A2 free; W13[nxt] stored

        // relu + stmatrix into A2: 2 mt x 2 col-halves, x4 each
        #pragma unroll
        for (int mt = 0; mt < 2; ++mt) {
            #pragma unroll
            for (int ch = 0; ch < 2; ++ch) {
                stm4(stA2 + mt * 16 * PIT2 * 2 + ch * 32,
                     relu_h2(acc1[mt][2 * ch][0],     acc1[mt][2 * ch][1]),
                     relu_h2(acc1[mt][2 * ch][2],     acc1[mt][2 * ch][3]),
                     relu_h2(acc1[mt][2 * ch + 1][0], acc1[mt][2 * ch + 1][1]),
                     relu_h2(acc1[mt][2 * ch + 1][2], acc1[mt][2 * ch + 1][3]));
            }
        }
        __syncthreads();   // (b) A2 visible

        // stage 2 partial: D2 += A2chunk @ W2chunk^T (K=128)
        #pragma unroll
        for (int ks = 0; ks < 8; ++ks) {
            uint32_t a0[4], a1[4], b[4];
            ldm4(a0, aA0 + ks * 32);
            ldm4(a1, aA1 + ks * 32);
            ldm4(b, uW2[cur] + w2off + ks * 32);
            mma16816(acc2[0][0], a0[0], a0[1], a0[2], a0[3], b[0], b[1]);
            mma16816(acc2[0][1], a0[0], a0[1], a0[2], a0[3], b[2], b[3]);
            mma16816(acc2[1][0], a1[0], a1[1], a1[2], a1[3], b[0], b[1]);
            mma16816(acc2[1][1], a1[0], a1[1], a1[2], a1[3], b[2], b[3]);
        }

        // store prefetched W2 into the other buffer
        if (hc < 3) {
            #pragma unroll
            for (int i = 0; i < 4; ++i) {
                const int idx = tid + i * NT;
                hstore4(w2p[nxt] + (idx >> 5) * PIT2 + (idx & 31) * 4, r2[i]);
            }
        }
    }

    // ---- A3 = relu(D2) -> fp16 into X buffer via stmatrix ----
    #pragma unroll
    for (int mt = 0; mt < 2; ++mt) {
        stm4(stX + mt * 16 * PITW * 2,
             relu_h2(acc2[mt][0][0], acc2[mt][0][1]),
             relu_h2(acc2[mt][0][2], acc2[mt][0][3]),
             relu_h2(acc2[mt][1][0], acc2[mt][1][1]),
             relu_h2(acc2[mt][1][2], acc2[mt][1][3]));
    }
    __syncthreads();   // A3 visible; w13p[0] holds W3 chunk 0 (stored at hc=3)

    // xn per accumulator row group: rows {g, 8+g, 16+g, 24+g}
    float xnv[4];
    #pragma unroll
    for (int i = 0; i < 4; ++i) xnv[i] = sXn[bq * 32 + i * 8 + g];

    // =================== Stage 3 over 4 H-chunks, fused epilogue ===================
    float rowSum[4] = {};
    #pragma unroll
    for (int hc = 0; hc < 4; ++hc) {
        const int cur = hc & 1, nxt = cur ^ 1;

        float4 r3[4];
        if (hc < 3) {
            const float* src = W3n + (hc + 1) * 128 * 128;
            #pragma unroll
            for (int i = 0; i < 4; ++i) {
                const int idx = tid + i * NT;
                r3[i] = *(const float4*)(src + (idx >> 4) * 128 + (idx & 15) * 4);
            }
        }

        float acc3[2][4][4] = {};
        gemm64_lm(aX0, aX1, uW13[cur] + w13off0, uW13[cur] + w13off1, acc3);

        // z = d3 + xn*w3col + b3 ; rowSum += relu(z)*w4
        #pragma unroll
        for (int j = 0; j < 4; ++j) {
            const int colb = hc * 128 + cc * 32 + j * 8 + tg * 2;
            const float4 e0 = sEpi[colb];
            const float4 e1 = sEpi[colb + 1];
            #pragma unroll
            for (int mt = 0; mt < 2; ++mt) {
                float z;
                z = acc3[mt][j][0] + xnv[mt * 2]     * e0.x + e0.y;   // row mt*16+g
                rowSum[mt * 2]     += fmaxf(z, 0.f) * e0.z;
                z = acc3[mt][j][1] + xnv[mt * 2]     * e1.x + e1.y;
                rowSum[mt * 2]     += fmaxf(z, 0.f) * e1.z;
                z = acc3[mt][j][2] + xnv[mt * 2 + 1] * e0.x + e0.y;   // row mt*16+8+g
                rowSum[mt * 2 + 1] += fmaxf(z, 0.f) * e0.z;
                z = acc3[mt][j][3] + xnv[mt * 2 + 1] * e1.x + e1.y;
                rowSum[mt * 2 + 1] += fmaxf(z, 0.f) * e1.z;
            }
        }

        if (hc < 3) {
            #pragma unroll
            for (int i = 0; i < 4; ++i) {
                const int idx = tid + i * NT;
                hstore4(w13p[nxt] + (idx >> 4) * PITW + (idx & 15) * 4, r3[i]);
            }
        }
        __syncthreads();   // W13[nxt] stored + this iter's readers done
    }

    // reduce over the 4 k-threads of each group, then over the 4 column quarters
    float* Pred = (float*)(sm + OFF_W2A);   // [4][128]
    #pragma unroll
    for (int i = 0; i < 4; ++i) {
        float v = rowSum[i];
        v += __shfl_xor_sync(0xffffffffu, v, 1);
        v += __shfl_xor_sync(0xffffffffu, v, 2);
        const int rr = bq * 32 + (i & 1) * 8 + (i >> 1) * 16 + g;
        if (tg == 0) Pred[cc * 128 + rr] = v;
    }
    __syncthreads();
    if (tid < 128) {
        const float tot = Pred[tid] + Pred[128 + tid] + Pred[256 + tid] + Pred[384 + tid];
        out[(r0 + tid) * NN + n] = fmaxf(tot + b4n, 0.0f);
    }
}

extern "C" void kernel_launch(void* const* d_in, const int* in_sizes, int n_in,
                              void* d_out, int out_size)
{
    const float* x  = (const float*)d_in[0];
    const float* W1 = (const float*)d_in[1];
    const float* W2 = (const float*)d_in[2];
    const float* W3 = (const float*)d_in[3];
    const float* b3 = (const float*)d_in[4];
    const float* W4 = (const float*)d_in[5];
    const float* b4 = (const float*)d_in[6];
    float* out = (float*)d_out;

    cudaFuncSetAttribute(ctp_hmma_kernel,
                         cudaFuncAttributeMaxDynamicSharedMemorySize, SMEM_BYTES);

    dim3 grid(NN, 1024 / TB);   // (64 nodes, 8 batch tiles of 128)
    ctp_hmma_kernel<<<grid, NT, SMEM_BYTES>>>(x, W1, W2, W3, b3, W4, b4, out);
}